// round 13
// baseline (speedup 1.0000x reference)
#include <cuda_runtime.h>
#include <cuda_fp16.h>
#include <cstdint>

// ---------------------------------------------------------------------------
// PMWA_24842090840472: 3-hop gated graph aggregation
// R13: hoist ALL threefry noise generation (3 hops) into the front kernel
//      (overlaps the issue-idle atomic fill); hops just load pre-scaled
//      noise. Hop kernel loses ~55% of its instructions.
// ---------------------------------------------------------------------------

#define DIMS 128
#define NMAX 65537
#define CAP 64

__device__ int g_count[NMAX];
__device__ int g_bkt[(size_t)NMAX * CAP];
// fp16 mirrors of h, ping-pong; row = 32 uint2 = 128 halves (dims in order)
__device__ uint2 g_h16[2][(size_t)NMAX * 32];
// pre-scaled noise (0.1*normal) for the 3 hops
__device__ float g_noise[3][(size_t)NMAX * 128];

// ---------------- Threefry-2x32 (JAX key schedule) -------------------------
#define TF_ROUND(x0, x1, r) \
    do { x0 += x1; x1 = ((x1) << (r)) | ((x1) >> (32 - (r))); x1 ^= x0; } while (0)

__host__ __device__ inline void tf2x32(uint32_t k0, uint32_t k1,
                                       uint32_t x0, uint32_t x1,
                                       uint32_t& o0, uint32_t& o1) {
    uint32_t ks0 = k0, ks1 = k1, ks2 = 0x1BD11BDAu ^ k0 ^ k1;
    x0 += ks0; x1 += ks1;
    TF_ROUND(x0, x1, 13); TF_ROUND(x0, x1, 15); TF_ROUND(x0, x1, 26); TF_ROUND(x0, x1, 6);
    x0 += ks1; x1 += ks2 + 1u;
    TF_ROUND(x0, x1, 17); TF_ROUND(x0, x1, 29); TF_ROUND(x0, x1, 16); TF_ROUND(x0, x1, 24);
    x0 += ks2; x1 += ks0 + 2u;
    TF_ROUND(x0, x1, 13); TF_ROUND(x0, x1, 15); TF_ROUND(x0, x1, 26); TF_ROUND(x0, x1, 6);
    x0 += ks0; x1 += ks1 + 3u;
    TF_ROUND(x0, x1, 17); TF_ROUND(x0, x1, 29); TF_ROUND(x0, x1, 16); TF_ROUND(x0, x1, 24);
    x0 += ks1; x1 += ks2 + 4u;
    TF_ROUND(x0, x1, 13); TF_ROUND(x0, x1, 15); TF_ROUND(x0, x1, 26); TF_ROUND(x0, x1, 6);
    x0 += ks2; x1 += ks0 + 5u;
    o0 = x0; o1 = x1;
}

// XLA/Giles float32 erfinv polynomial
__device__ inline float erfinv_xla(float x) {
    float w = -__logf(fmaf(-x, x, 1.0f));
    float p;
    if (w < 5.0f) {
        w -= 2.5f;
        p = 2.81022636e-08f;
        p = fmaf(p, w, 3.43273939e-07f);
        p = fmaf(p, w, -3.5233877e-06f);
        p = fmaf(p, w, -4.39150654e-06f);
        p = fmaf(p, w, 0.00021858087f);
        p = fmaf(p, w, -0.00125372503f);
        p = fmaf(p, w, -0.00417768164f);
        p = fmaf(p, w, 0.246640727f);
        p = fmaf(p, w, 1.50140941f);
    } else {
        w = sqrtf(w) - 3.0f;
        p = -0.000200214257f;
        p = fmaf(p, w, 0.000100950558f);
        p = fmaf(p, w, 0.00134934322f);
        p = fmaf(p, w, -0.00367342844f);
        p = fmaf(p, w, 0.00573950773f);
        p = fmaf(p, w, -0.0076224613f);
        p = fmaf(p, w, 0.00943887047f);
        p = fmaf(p, w, 1.00167406f);
        p = fmaf(p, w, 2.83297682f);
    }
    return p * x;
}

__device__ inline float tf_normal(uint32_t k0, uint32_t k1, uint32_t idx) {
    uint32_t o0, o1;
    tf2x32(k0, k1, 0u, idx, o0, o1);
    uint32_t bits = o0 ^ o1;
    float f = __uint_as_float(0x3f800000u | (bits >> 9)) - 1.0f;
    float u = fmaf(f, 2.0f, -0.99999994f);
    return 1.41421354f * erfinv_xla(u);
}

// ---------------- helpers --------------------------------------------------
#define BFLY32(d)                                       \
    d += __shfl_xor_sync(0xffffffffu, d, 16);           \
    d += __shfl_xor_sync(0xffffffffu, d, 8);            \
    d += __shfl_xor_sync(0xffffffffu, d, 4);            \
    d += __shfl_xor_sync(0xffffffffu, d, 2);            \
    d += __shfl_xor_sync(0xffffffffu, d, 1);

#define SEGRED(d)                                       \
    d += __shfl_xor_sync(0xffffffffu, d, 8);            \
    d += __shfl_xor_sync(0xffffffffu, d, 4);            \
    d += __shfl_xor_sync(0xffffffffu, d, 2);            \
    d += __shfl_xor_sync(0xffffffffu, d, 1);

__device__ __forceinline__ float sigm(float d) {
    return 1.0f / (1.0f + __expf(-d));
}

__device__ __forceinline__ uint2 f4_to_h4(float4 a) {
    __half2 p0 = __floats2half2_rn(a.x, a.y);
    __half2 p1 = __floats2half2_rn(a.z, a.w);
    uint2 u;
    u.x = *(uint32_t*)&p0;
    u.y = *(uint32_t*)&p1;
    return u;
}

// partial dot over this lane's 8 dims (uint4 = 4 half2), fp16 products/f32 tail
__device__ __forceinline__ float dot8(uint4 v, __half2 h0, __half2 h1,
                                      __half2 h2, __half2 h3) {
    __half2 p = __hmul2(*(__half2*)&v.x, h0);
    p = __hfma2(*(__half2*)&v.y, h1, p);
    p = __hfma2(*(__half2*)&v.z, h2, p);
    p = __hfma2(*(__half2*)&v.w, h3, p);
    float2 f = __half22float2(p);
    return f.x + f.y;
}

__device__ __forceinline__ void accum8(float* acc, uint4 v, float a) {
    float2 f0 = __half22float2(*(__half2*)&v.x);
    float2 f1 = __half22float2(*(__half2*)&v.y);
    float2 f2 = __half22float2(*(__half2*)&v.z);
    float2 f3 = __half22float2(*(__half2*)&v.w);
    acc[0] = fmaf(a, f0.x, acc[0]);
    acc[1] = fmaf(a, f0.y, acc[1]);
    acc[2] = fmaf(a, f1.x, acc[2]);
    acc[3] = fmaf(a, f1.y, acc[3]);
    acc[4] = fmaf(a, f2.x, acc[4]);
    acc[5] = fmaf(a, f2.y, acc[5]);
    acc[6] = fmaf(a, f3.x, acc[6]);
    acc[7] = fmaf(a, f3.y, acc[7]);
}

// ---------------- CSR zero -------------------------------------------------
__global__ void k_zero(int N) {
    int i = blockIdx.x * blockDim.x + threadIdx.x;
    if (i < N) g_count[i] = 0;
}

// - fused front: bucket fill | normalize x | 3-hop noise precompute ---------
__global__ void k_front(const int* __restrict__ src, const int* __restrict__ dst,
                        int E, const float* __restrict__ x,
                        float* __restrict__ out, int N,
                        int fillBlocks, int normBlocks, int blocksPerHop,
                        uint32_t ka0, uint32_t ka1, uint32_t kb0, uint32_t kb1,
                        uint32_t kc0, uint32_t kc1) {
    int b = blockIdx.x;
    if (b < fillBlocks) {
        // ---- bucket CSR fill (atomic-bound) ----
        int i = (b * blockDim.x + threadIdx.x) * 2;
        if (i + 1 < E) {
            int2 d = *(const int2*)(dst + i);
            int2 s = *(const int2*)(src + i);
            int p0 = atomicAdd(&g_count[d.x], 1);
            if (p0 < CAP) g_bkt[(size_t)d.x * CAP + p0] = s.x;
            int p1 = atomicAdd(&g_count[d.y], 1);
            if (p1 < CAP) g_bkt[(size_t)d.y * CAP + p1] = s.y;
        } else if (i < E) {
            int d = dst[i];
            int p = atomicAdd(&g_count[d], 1);
            if (p < CAP) g_bkt[(size_t)d * CAP + p] = src[i];
        }
    } else if (b < fillBlocks + normBlocks) {
        // ---- normalize(x) -> out[0] + fp16 mirror ----
        int warp = ((b - fillBlocks) * blockDim.x + threadIdx.x) >> 5;
        int lane = threadIdx.x & 31;
        if (warp >= N) return;
        const float4* sv = (const float4*)x;
        float4 a = sv[(size_t)warp * 32 + lane];
        float ss = fmaf(a.x, a.x, fmaf(a.y, a.y, fmaf(a.z, a.z, a.w * a.w)));
        BFLY32(ss);
        float inv = 1.0f / fmaxf(sqrtf(ss), 1e-12f);
        a.x *= inv; a.y *= inv; a.z *= inv; a.w *= inv;
        ((float4*)out)[(size_t)warp * 32 + lane] = a;
        g_h16[0][(size_t)warp * 32 + lane] = f4_to_h4(a);
    } else {
        // ---- noise precompute: 0.1*normal for hop k (compute-bound) ----
        int nb2 = b - fillBlocks - normBlocks;
        int k = nb2 / blocksPerHop;
        int rb = nb2 - k * blocksPerHop;
        int t = rb * (int)blockDim.x + threadIdx.x;     // float4 index
        uint32_t base = (uint32_t)t * 4u;
        uint32_t nd = (uint32_t)N * 128u;
        if (base >= nd) return;
        uint32_t k0 = (k == 0) ? ka0 : ((k == 1) ? kb0 : kc0);
        uint32_t k1 = (k == 0) ? ka1 : ((k == 1) ? kb1 : kc1);
        float4 nz;
        nz.x = 0.1f * tf_normal(k0, k1, base + 0u);
        nz.y = 0.1f * tf_normal(k0, k1, base + 1u);
        nz.z = 0.1f * tf_normal(k0, k1, base + 2u);
        nz.w = 0.1f * tf_normal(k0, k1, base + 3u);
        ((float4*)g_noise[k])[t] = nz;
    }
}

// ---- fused hop: segment-16 gather/gate + (preload) noise + normalize -------
__global__ void __launch_bounds__(256) k_hop(float* __restrict__ out, int N,
                                             int selin, int selout, int hopk) {
    __shared__ float xch[8][128];
    int wslot = threadIdx.x >> 5;
    int node = (blockIdx.x * blockDim.x + threadIdx.x) >> 5;
    int lane = threadIdx.x & 31;
    if (node >= N) return;
    int seg = lane >> 4;       // which edge of the pair this lane works on
    int sl = lane & 15;        // lane within segment; owns dims sl*8..sl*8+7
    const uint4* __restrict__ hv = (const uint4*)g_h16[selin];   // 16 uint4/row

    uint4 hdu = __ldg(&hv[(size_t)node * 16 + sl]);
    __half2 h0 = *(__half2*)&hdu.x, h1 = *(__half2*)&hdu.y;
    __half2 h2 = *(__half2*)&hdu.z, h3 = *(__half2*)&hdu.w;
    float acc[8] = {0.f, 0.f, 0.f, 0.f, 0.f, 0.f, 0.f, 0.f};

    int cnt = min(g_count[node], CAP);
    const int* bkt = g_bkt + (size_t)node * CAP;
    int e = 0;

    // 4 edges per iteration (2 segment-pairs in flight)
    for (; e + 4 <= cnt; e += 4) {
        int sA = __ldg(&bkt[e + seg]);
        int sB = __ldg(&bkt[e + 2 + seg]);
        uint4 vA = __ldg(&hv[(size_t)sA * 16 + sl]);
        uint4 vB = __ldg(&hv[(size_t)sB * 16 + sl]);
        float dA = dot8(vA, h0, h1, h2, h3);
        float dB = dot8(vB, h0, h1, h2, h3);
        #pragma unroll
        for (int off = 8; off >= 1; off >>= 1) {
            dA += __shfl_xor_sync(0xffffffffu, dA, off);
            dB += __shfl_xor_sync(0xffffffffu, dB, off);
        }
        accum8(acc, vA, sigm(dA));
        accum8(acc, vB, sigm(dB));
    }
    if (e + 2 <= cnt) {
        int sA = __ldg(&bkt[e + seg]);
        uint4 vA = __ldg(&hv[(size_t)sA * 16 + sl]);
        float dA = dot8(vA, h0, h1, h2, h3);
        SEGRED(dA);
        accum8(acc, vA, sigm(dA));
        e += 2;
    }
    if (e < cnt) {
        int s = __ldg(&bkt[e]);               // both segments same edge
        uint4 v = __ldg(&hv[(size_t)s * 16 + sl]);
        float d = dot8(v, h0, h1, h2, h3);
        SEGRED(d);
        float a = (seg == 0) ? sigm(d) : 0.f; // avoid double count
        accum8(acc, v, a);
    }

    // cross-segment sum
    #pragma unroll
    for (int i = 0; i < 8; i++)
        acc[i] += __shfl_xor_sync(0xffffffffu, acc[i], 16);

    // layout exchange: dims sl*8..+7 -> float4 per lane over 32 lanes
    if (seg == 0) {
        #pragma unroll
        for (int i = 0; i < 8; i++) xch[wslot][sl * 8 + i] = acc[i];
    }
    __syncwarp();
    float4 r = ((float4*)xch[wslot])[lane];

    // + precomputed 0.1*normal, l2-normalize, store f32 out + fp16 mirror
    float4 nz = __ldg(&((const float4*)g_noise[hopk])[(size_t)node * 32 + lane]);
    r.x += nz.x; r.y += nz.y; r.z += nz.z; r.w += nz.w;
    float ss = fmaf(r.x, r.x, fmaf(r.y, r.y, fmaf(r.z, r.z, r.w * r.w)));
    BFLY32(ss);
    float inv = 1.0f / fmaxf(sqrtf(ss), 1e-12f);
    r.x *= inv; r.y *= inv; r.z *= inv; r.w *= inv;
    ((float4*)out)[(size_t)node * 32 + lane] = r;
    g_h16[selout][(size_t)node * 32 + lane] = f4_to_h4(r);
}

// ---------------------------------------------------------------------------
extern "C" void kernel_launch(void* const* d_in, const int* in_sizes, int n_in,
                              void* d_out, int out_size) {
    const float* x = (const float*)d_in[0];
    const int* ei = (const int*)d_in[1];      // int32 (JAX x64 disabled)
    int N = in_sizes[0] / DIMS;
    int E = in_sizes[1] / 2;
    float* out = (float*)d_out;
    size_t ND = (size_t)N * DIMS;

    uint32_t hk[3][2];
    for (uint32_t i = 0; i < 3; i++) {
        tf2x32(0u, 1u, 0u, i, hk[i][0], hk[i][1]);
    }

    const int* src = ei;
    const int* dst = ei + E;

    int fillBlocks = ((E + 1) / 2 + 255) / 256;
    int nb = (N + 255) / 256;
    int wNodes = (N + 7) / 8;               // norm blocks (8 warps each)
    int blocksPerHop = ((N * DIMS / 4) + 255) / 256;

    // zero counts, then fused [fill | normalize | noise x3]
    k_zero<<<nb, 256>>>(N);
    k_front<<<fillBlocks + wNodes + 3 * blocksPerHop, 256>>>(
        src, dst, E, x, out, N, fillBlocks, wNodes, blocksPerHop,
        hk[0][0], hk[0][1], hk[1][0], hk[1][1], hk[2][0], hk[2][1]);

    // 3 fused hops, ping-pong mirrors
    for (int k = 0; k < 3; k++) {
        float* nxt = out + (size_t)(k + 1) * ND;
        k_hop<<<wNodes, 256>>>(nxt, N, k & 1, (k + 1) & 1, k);
    }
}

// round 15
// speedup vs baseline: 1.0406x; 1.0406x over previous
#include <cuda_runtime.h>
#include <cuda_fp16.h>
#include <cstdint>

// ---------------------------------------------------------------------------
// PMWA_24842090840472: 3-hop gated graph aggregation
// R14: pipelined noise — hop k's kernel co-schedules noise[k+1] generation
//      in extra blocks (fills the lean hop's 38% idle issue slots);
//      front computes noise[0] overlapped with fill+norm. Lean hop = R13's.
// ---------------------------------------------------------------------------

#define DIMS 128
#define NMAX 65537
#define CAP 64

__device__ int g_count[NMAX];
__device__ int g_bkt[(size_t)NMAX * CAP];
// fp16 mirrors of h, ping-pong; row = 32 uint2 = 128 halves (dims in order)
__device__ uint2 g_h16[2][(size_t)NMAX * 32];
// pre-scaled noise (0.1*normal) for the 3 hops
__device__ float g_noise[3][(size_t)NMAX * 128];

// ---------------- Threefry-2x32 (JAX key schedule) -------------------------
#define TF_ROUND(x0, x1, r) \
    do { x0 += x1; x1 = ((x1) << (r)) | ((x1) >> (32 - (r))); x1 ^= x0; } while (0)

__host__ __device__ inline void tf2x32(uint32_t k0, uint32_t k1,
                                       uint32_t x0, uint32_t x1,
                                       uint32_t& o0, uint32_t& o1) {
    uint32_t ks0 = k0, ks1 = k1, ks2 = 0x1BD11BDAu ^ k0 ^ k1;
    x0 += ks0; x1 += ks1;
    TF_ROUND(x0, x1, 13); TF_ROUND(x0, x1, 15); TF_ROUND(x0, x1, 26); TF_ROUND(x0, x1, 6);
    x0 += ks1; x1 += ks2 + 1u;
    TF_ROUND(x0, x1, 17); TF_ROUND(x0, x1, 29); TF_ROUND(x0, x1, 16); TF_ROUND(x0, x1, 24);
    x0 += ks2; x1 += ks0 + 2u;
    TF_ROUND(x0, x1, 13); TF_ROUND(x0, x1, 15); TF_ROUND(x0, x1, 26); TF_ROUND(x0, x1, 6);
    x0 += ks0; x1 += ks1 + 3u;
    TF_ROUND(x0, x1, 17); TF_ROUND(x0, x1, 29); TF_ROUND(x0, x1, 16); TF_ROUND(x0, x1, 24);
    x0 += ks1; x1 += ks2 + 4u;
    TF_ROUND(x0, x1, 13); TF_ROUND(x0, x1, 15); TF_ROUND(x0, x1, 26); TF_ROUND(x0, x1, 6);
    x0 += ks2; x1 += ks0 + 5u;
    o0 = x0; o1 = x1;
}

// XLA/Giles float32 erfinv polynomial
__device__ inline float erfinv_xla(float x) {
    float w = -__logf(fmaf(-x, x, 1.0f));
    float p;
    if (w < 5.0f) {
        w -= 2.5f;
        p = 2.81022636e-08f;
        p = fmaf(p, w, 3.43273939e-07f);
        p = fmaf(p, w, -3.5233877e-06f);
        p = fmaf(p, w, -4.39150654e-06f);
        p = fmaf(p, w, 0.00021858087f);
        p = fmaf(p, w, -0.00125372503f);
        p = fmaf(p, w, -0.00417768164f);
        p = fmaf(p, w, 0.246640727f);
        p = fmaf(p, w, 1.50140941f);
    } else {
        w = sqrtf(w) - 3.0f;
        p = -0.000200214257f;
        p = fmaf(p, w, 0.000100950558f);
        p = fmaf(p, w, 0.00134934322f);
        p = fmaf(p, w, -0.00367342844f);
        p = fmaf(p, w, 0.00573950773f);
        p = fmaf(p, w, -0.0076224613f);
        p = fmaf(p, w, 0.00943887047f);
        p = fmaf(p, w, 1.00167406f);
        p = fmaf(p, w, 2.83297682f);
    }
    return p * x;
}

__device__ inline float tf_normal(uint32_t k0, uint32_t k1, uint32_t idx) {
    uint32_t o0, o1;
    tf2x32(k0, k1, 0u, idx, o0, o1);
    uint32_t bits = o0 ^ o1;
    float f = __uint_as_float(0x3f800000u | (bits >> 9)) - 1.0f;
    float u = fmaf(f, 2.0f, -0.99999994f);
    return 1.41421354f * erfinv_xla(u);
}

// write one float4 of pre-scaled noise for hop k at float4-index t
__device__ __forceinline__ void gen_noise4(int k, int t, uint32_t k0, uint32_t k1,
                                           uint32_t nd) {
    uint32_t base = (uint32_t)t * 4u;
    if (base >= nd) return;
    float4 nz;
    nz.x = 0.1f * tf_normal(k0, k1, base + 0u);
    nz.y = 0.1f * tf_normal(k0, k1, base + 1u);
    nz.z = 0.1f * tf_normal(k0, k1, base + 2u);
    nz.w = 0.1f * tf_normal(k0, k1, base + 3u);
    ((float4*)g_noise[k])[t] = nz;
}

// ---------------- helpers --------------------------------------------------
#define BFLY32(d)                                       \
    d += __shfl_xor_sync(0xffffffffu, d, 16);           \
    d += __shfl_xor_sync(0xffffffffu, d, 8);            \
    d += __shfl_xor_sync(0xffffffffu, d, 4);            \
    d += __shfl_xor_sync(0xffffffffu, d, 2);            \
    d += __shfl_xor_sync(0xffffffffu, d, 1);

#define SEGRED(d)                                       \
    d += __shfl_xor_sync(0xffffffffu, d, 8);            \
    d += __shfl_xor_sync(0xffffffffu, d, 4);            \
    d += __shfl_xor_sync(0xffffffffu, d, 2);            \
    d += __shfl_xor_sync(0xffffffffu, d, 1);

__device__ __forceinline__ float sigm(float d) {
    return 1.0f / (1.0f + __expf(-d));
}

__device__ __forceinline__ uint2 f4_to_h4(float4 a) {
    __half2 p0 = __floats2half2_rn(a.x, a.y);
    __half2 p1 = __floats2half2_rn(a.z, a.w);
    uint2 u;
    u.x = *(uint32_t*)&p0;
    u.y = *(uint32_t*)&p1;
    return u;
}

// partial dot over this lane's 8 dims (uint4 = 4 half2), fp16 products/f32 tail
__device__ __forceinline__ float dot8(uint4 v, __half2 h0, __half2 h1,
                                      __half2 h2, __half2 h3) {
    __half2 p = __hmul2(*(__half2*)&v.x, h0);
    p = __hfma2(*(__half2*)&v.y, h1, p);
    p = __hfma2(*(__half2*)&v.z, h2, p);
    p = __hfma2(*(__half2*)&v.w, h3, p);
    float2 f = __half22float2(p);
    return f.x + f.y;
}

__device__ __forceinline__ void accum8(float* acc, uint4 v, float a) {
    float2 f0 = __half22float2(*(__half2*)&v.x);
    float2 f1 = __half22float2(*(__half2*)&v.y);
    float2 f2 = __half22float2(*(__half2*)&v.z);
    float2 f3 = __half22float2(*(__half2*)&v.w);
    acc[0] = fmaf(a, f0.x, acc[0]);
    acc[1] = fmaf(a, f0.y, acc[1]);
    acc[2] = fmaf(a, f1.x, acc[2]);
    acc[3] = fmaf(a, f1.y, acc[3]);
    acc[4] = fmaf(a, f2.x, acc[4]);
    acc[5] = fmaf(a, f2.y, acc[5]);
    acc[6] = fmaf(a, f3.x, acc[6]);
    acc[7] = fmaf(a, f3.y, acc[7]);
}

// ---------------- CSR zero -------------------------------------------------
__global__ void k_zero(int N) {
    int i = blockIdx.x * blockDim.x + threadIdx.x;
    if (i < N) g_count[i] = 0;
}

// - fused front: bucket fill | normalize x | noise[0] precompute ------------
__global__ void k_front(const int* __restrict__ src, const int* __restrict__ dst,
                        int E, const float* __restrict__ x,
                        float* __restrict__ out, int N,
                        int fillBlocks, int normBlocks,
                        uint32_t ka0, uint32_t ka1) {
    int b = blockIdx.x;
    if (b < fillBlocks) {
        int i = (b * blockDim.x + threadIdx.x) * 2;
        if (i + 1 < E) {
            int2 d = *(const int2*)(dst + i);
            int2 s = *(const int2*)(src + i);
            int p0 = atomicAdd(&g_count[d.x], 1);
            if (p0 < CAP) g_bkt[(size_t)d.x * CAP + p0] = s.x;
            int p1 = atomicAdd(&g_count[d.y], 1);
            if (p1 < CAP) g_bkt[(size_t)d.y * CAP + p1] = s.y;
        } else if (i < E) {
            int d = dst[i];
            int p = atomicAdd(&g_count[d], 1);
            if (p < CAP) g_bkt[(size_t)d * CAP + p] = src[i];
        }
    } else if (b < fillBlocks + normBlocks) {
        int warp = ((b - fillBlocks) * blockDim.x + threadIdx.x) >> 5;
        int lane = threadIdx.x & 31;
        if (warp >= N) return;
        const float4* sv = (const float4*)x;
        float4 a = sv[(size_t)warp * 32 + lane];
        float ss = fmaf(a.x, a.x, fmaf(a.y, a.y, fmaf(a.z, a.z, a.w * a.w)));
        BFLY32(ss);
        float inv = 1.0f / fmaxf(sqrtf(ss), 1e-12f);
        a.x *= inv; a.y *= inv; a.z *= inv; a.w *= inv;
        ((float4*)out)[(size_t)warp * 32 + lane] = a;
        g_h16[0][(size_t)warp * 32 + lane] = f4_to_h4(a);
    } else {
        int t = (b - fillBlocks - normBlocks) * (int)blockDim.x + threadIdx.x;
        gen_noise4(0, t, ka0, ka1, (uint32_t)N * 128u);
    }
}

// ---- fused hop: [hop blocks: gather/gate + noise add + normalize]
//                 [extra blocks: generate noise for hop knext] --------------
__global__ void __launch_bounds__(256) k_hop(float* __restrict__ out, int N,
                                             int selin, int selout, int hopk,
                                             int hopBlocks,
                                             uint32_t kn0, uint32_t kn1) {
    if ((int)blockIdx.x >= hopBlocks) {
        // noise generation for hop hopk+1 (disjoint buffer, no race)
        int t = ((int)blockIdx.x - hopBlocks) * (int)blockDim.x + threadIdx.x;
        gen_noise4(hopk + 1, t, kn0, kn1, (uint32_t)N * 128u);
        return;
    }
    __shared__ float xch[8][128];
    int wslot = threadIdx.x >> 5;
    int node = (blockIdx.x * blockDim.x + threadIdx.x) >> 5;
    int lane = threadIdx.x & 31;
    if (node >= N) return;
    int seg = lane >> 4;       // which edge of the pair this lane works on
    int sl = lane & 15;        // lane within segment; owns dims sl*8..sl*8+7
    const uint4* __restrict__ hv = (const uint4*)g_h16[selin];   // 16 uint4/row

    uint4 hdu = __ldg(&hv[(size_t)node * 16 + sl]);
    __half2 h0 = *(__half2*)&hdu.x, h1 = *(__half2*)&hdu.y;
    __half2 h2 = *(__half2*)&hdu.z, h3 = *(__half2*)&hdu.w;
    float acc[8] = {0.f, 0.f, 0.f, 0.f, 0.f, 0.f, 0.f, 0.f};

    int cnt = min(g_count[node], CAP);
    const int* bkt = g_bkt + (size_t)node * CAP;
    int e = 0;

    // 4 edges per iteration (2 segment-pairs in flight)
    for (; e + 4 <= cnt; e += 4) {
        int sA = __ldg(&bkt[e + seg]);
        int sB = __ldg(&bkt[e + 2 + seg]);
        uint4 vA = __ldg(&hv[(size_t)sA * 16 + sl]);
        uint4 vB = __ldg(&hv[(size_t)sB * 16 + sl]);
        float dA = dot8(vA, h0, h1, h2, h3);
        float dB = dot8(vB, h0, h1, h2, h3);
        #pragma unroll
        for (int off = 8; off >= 1; off >>= 1) {
            dA += __shfl_xor_sync(0xffffffffu, dA, off);
            dB += __shfl_xor_sync(0xffffffffu, dB, off);
        }
        accum8(acc, vA, sigm(dA));
        accum8(acc, vB, sigm(dB));
    }
    if (e + 2 <= cnt) {
        int sA = __ldg(&bkt[e + seg]);
        uint4 vA = __ldg(&hv[(size_t)sA * 16 + sl]);
        float dA = dot8(vA, h0, h1, h2, h3);
        SEGRED(dA);
        accum8(acc, vA, sigm(dA));
        e += 2;
    }
    if (e < cnt) {
        int s = __ldg(&bkt[e]);               // both segments same edge
        uint4 v = __ldg(&hv[(size_t)s * 16 + sl]);
        float d = dot8(v, h0, h1, h2, h3);
        SEGRED(d);
        float a = (seg == 0) ? sigm(d) : 0.f; // avoid double count
        accum8(acc, v, a);
    }

    // cross-segment sum
    #pragma unroll
    for (int i = 0; i < 8; i++)
        acc[i] += __shfl_xor_sync(0xffffffffu, acc[i], 16);

    // layout exchange: dims sl*8..+7 -> float4 per lane over 32 lanes
    if (seg == 0) {
        #pragma unroll
        for (int i = 0; i < 8; i++) xch[wslot][sl * 8 + i] = acc[i];
    }
    __syncwarp();
    float4 r = ((float4*)xch[wslot])[lane];

    // + precomputed 0.1*normal, l2-normalize, store f32 out + fp16 mirror
    float4 nz = __ldg(&((const float4*)g_noise[hopk])[(size_t)node * 32 + lane]);
    r.x += nz.x; r.y += nz.y; r.z += nz.z; r.w += nz.w;
    float ss = fmaf(r.x, r.x, fmaf(r.y, r.y, fmaf(r.z, r.z, r.w * r.w)));
    BFLY32(ss);
    float inv = 1.0f / fmaxf(sqrtf(ss), 1e-12f);
    r.x *= inv; r.y *= inv; r.z *= inv; r.w *= inv;
    ((float4*)out)[(size_t)node * 32 + lane] = r;
    g_h16[selout][(size_t)node * 32 + lane] = f4_to_h4(r);
}

// ---------------------------------------------------------------------------
extern "C" void kernel_launch(void* const* d_in, const int* in_sizes, int n_in,
                              void* d_out, int out_size) {
    const float* x = (const float*)d_in[0];
    const int* ei = (const int*)d_in[1];      // int32 (JAX x64 disabled)
    int N = in_sizes[0] / DIMS;
    int E = in_sizes[1] / 2;
    float* out = (float*)d_out;
    size_t ND = (size_t)N * DIMS;

    uint32_t hk[3][2];
    for (uint32_t i = 0; i < 3; i++) {
        tf2x32(0u, 1u, 0u, i, hk[i][0], hk[i][1]);
    }

    const int* src = ei;
    const int* dst = ei + E;

    int fillBlocks = ((E + 1) / 2 + 255) / 256;
    int nb = (N + 255) / 256;
    int wNodes = (N + 7) / 8;               // hop / norm blocks (8 warps each)
    int bph = ((N * DIMS / 4) + 255) / 256; // noise blocks per hop

    // zero counts, then fused [fill | normalize | noise0]
    k_zero<<<nb, 256>>>(N);
    k_front<<<fillBlocks + wNodes + bph, 256>>>(
        src, dst, E, x, out, N, fillBlocks, wNodes, hk[0][0], hk[0][1]);

    // 3 fused hops; hop k also generates noise[k+1] (k<2)
    for (int k = 0; k < 3; k++) {
        float* nxt = out + (size_t)(k + 1) * ND;
        int extra = (k < 2) ? bph : 0;
        uint32_t kn0 = (k < 2) ? hk[k + 1][0] : 0u;
        uint32_t kn1 = (k < 2) ? hk[k + 1][1] : 0u;
        k_hop<<<wNodes + extra, 256>>>(nxt, N, k & 1, (k + 1) & 1, k,
                                       wNodes, kn0, kn1);
    }
}

// round 16
// speedup vs baseline: 1.0591x; 1.0177x over previous
#include <cuda_runtime.h>
#include <cuda_fp16.h>
#include <cstdint>

// ---------------------------------------------------------------------------
// PMWA_24842090840472: 3-hop gated graph aggregation
// R16: R12 base (inline noise epilogue — proven cheapest placement) +
//      (a) threefry normals hoisted to kernel top (ILP for edge-loop stalls)
//      (b) software-pipelined edge loop (prefetch next quad)
//      (c) no fp16 mirror write on last hop.
// ---------------------------------------------------------------------------

#define DIMS 128
#define NMAX 65537
#define CAP 64

__device__ int g_count[NMAX];
__device__ int g_bkt[(size_t)NMAX * CAP];
// fp16 mirrors of h, ping-pong; row = 32 uint2 = 128 halves (dims in order)
__device__ uint2 g_h16[2][(size_t)NMAX * 32];

// ---------------- Threefry-2x32 (JAX key schedule) -------------------------
#define TF_ROUND(x0, x1, r) \
    do { x0 += x1; x1 = ((x1) << (r)) | ((x1) >> (32 - (r))); x1 ^= x0; } while (0)

__host__ __device__ inline void tf2x32(uint32_t k0, uint32_t k1,
                                       uint32_t x0, uint32_t x1,
                                       uint32_t& o0, uint32_t& o1) {
    uint32_t ks0 = k0, ks1 = k1, ks2 = 0x1BD11BDAu ^ k0 ^ k1;
    x0 += ks0; x1 += ks1;
    TF_ROUND(x0, x1, 13); TF_ROUND(x0, x1, 15); TF_ROUND(x0, x1, 26); TF_ROUND(x0, x1, 6);
    x0 += ks1; x1 += ks2 + 1u;
    TF_ROUND(x0, x1, 17); TF_ROUND(x0, x1, 29); TF_ROUND(x0, x1, 16); TF_ROUND(x0, x1, 24);
    x0 += ks2; x1 += ks0 + 2u;
    TF_ROUND(x0, x1, 13); TF_ROUND(x0, x1, 15); TF_ROUND(x0, x1, 26); TF_ROUND(x0, x1, 6);
    x0 += ks0; x1 += ks1 + 3u;
    TF_ROUND(x0, x1, 17); TF_ROUND(x0, x1, 29); TF_ROUND(x0, x1, 16); TF_ROUND(x0, x1, 24);
    x0 += ks1; x1 += ks2 + 4u;
    TF_ROUND(x0, x1, 13); TF_ROUND(x0, x1, 15); TF_ROUND(x0, x1, 26); TF_ROUND(x0, x1, 6);
    x0 += ks2; x1 += ks0 + 5u;
    o0 = x0; o1 = x1;
}

// XLA/Giles float32 erfinv polynomial
__device__ inline float erfinv_xla(float x) {
    float w = -__logf(fmaf(-x, x, 1.0f));
    float p;
    if (w < 5.0f) {
        w -= 2.5f;
        p = 2.81022636e-08f;
        p = fmaf(p, w, 3.43273939e-07f);
        p = fmaf(p, w, -3.5233877e-06f);
        p = fmaf(p, w, -4.39150654e-06f);
        p = fmaf(p, w, 0.00021858087f);
        p = fmaf(p, w, -0.00125372503f);
        p = fmaf(p, w, -0.00417768164f);
        p = fmaf(p, w, 0.246640727f);
        p = fmaf(p, w, 1.50140941f);
    } else {
        w = sqrtf(w) - 3.0f;
        p = -0.000200214257f;
        p = fmaf(p, w, 0.000100950558f);
        p = fmaf(p, w, 0.00134934322f);
        p = fmaf(p, w, -0.00367342844f);
        p = fmaf(p, w, 0.00573950773f);
        p = fmaf(p, w, -0.0076224613f);
        p = fmaf(p, w, 0.00943887047f);
        p = fmaf(p, w, 1.00167406f);
        p = fmaf(p, w, 2.83297682f);
    }
    return p * x;
}

__device__ inline float tf_normal(uint32_t k0, uint32_t k1, uint32_t idx) {
    uint32_t o0, o1;
    tf2x32(k0, k1, 0u, idx, o0, o1);
    uint32_t bits = o0 ^ o1;
    float f = __uint_as_float(0x3f800000u | (bits >> 9)) - 1.0f;
    float u = fmaf(f, 2.0f, -0.99999994f);
    return 1.41421354f * erfinv_xla(u);
}

// ---------------- helpers --------------------------------------------------
#define BFLY32(d)                                       \
    d += __shfl_xor_sync(0xffffffffu, d, 16);           \
    d += __shfl_xor_sync(0xffffffffu, d, 8);            \
    d += __shfl_xor_sync(0xffffffffu, d, 4);            \
    d += __shfl_xor_sync(0xffffffffu, d, 2);            \
    d += __shfl_xor_sync(0xffffffffu, d, 1);

#define SEGRED(d)                                       \
    d += __shfl_xor_sync(0xffffffffu, d, 8);            \
    d += __shfl_xor_sync(0xffffffffu, d, 4);            \
    d += __shfl_xor_sync(0xffffffffu, d, 2);            \
    d += __shfl_xor_sync(0xffffffffu, d, 1);

__device__ __forceinline__ float sigm(float d) {
    return 1.0f / (1.0f + __expf(-d));
}

__device__ __forceinline__ uint2 f4_to_h4(float4 a) {
    __half2 p0 = __floats2half2_rn(a.x, a.y);
    __half2 p1 = __floats2half2_rn(a.z, a.w);
    uint2 u;
    u.x = *(uint32_t*)&p0;
    u.y = *(uint32_t*)&p1;
    return u;
}

// partial dot over this lane's 8 dims (uint4 = 4 half2), fp16 products/f32 tail
__device__ __forceinline__ float dot8(uint4 v, __half2 h0, __half2 h1,
                                      __half2 h2, __half2 h3) {
    __half2 p = __hmul2(*(__half2*)&v.x, h0);
    p = __hfma2(*(__half2*)&v.y, h1, p);
    p = __hfma2(*(__half2*)&v.z, h2, p);
    p = __hfma2(*(__half2*)&v.w, h3, p);
    float2 f = __half22float2(p);
    return f.x + f.y;
}

__device__ __forceinline__ void accum8(float* acc, uint4 v, float a) {
    float2 f0 = __half22float2(*(__half2*)&v.x);
    float2 f1 = __half22float2(*(__half2*)&v.y);
    float2 f2 = __half22float2(*(__half2*)&v.z);
    float2 f3 = __half22float2(*(__half2*)&v.w);
    acc[0] = fmaf(a, f0.x, acc[0]);
    acc[1] = fmaf(a, f0.y, acc[1]);
    acc[2] = fmaf(a, f1.x, acc[2]);
    acc[3] = fmaf(a, f1.y, acc[3]);
    acc[4] = fmaf(a, f2.x, acc[4]);
    acc[5] = fmaf(a, f2.y, acc[5]);
    acc[6] = fmaf(a, f3.x, acc[6]);
    acc[7] = fmaf(a, f3.y, acc[7]);
}

// ---------------- CSR zero -------------------------------------------------
__global__ void k_zero(int N) {
    int i = blockIdx.x * blockDim.x + threadIdx.x;
    if (i < N) g_count[i] = 0;
}

// ------- fused: bucket fill (first fillBlocks) | normalize x (rest) --------
__global__ void k_front(const int* __restrict__ src, const int* __restrict__ dst,
                        int E, const float* __restrict__ x,
                        float* __restrict__ out, int N, int fillBlocks) {
    if ((int)blockIdx.x < fillBlocks) {
        int i = (blockIdx.x * blockDim.x + threadIdx.x) * 2;
        if (i + 1 < E) {
            int2 d = *(const int2*)(dst + i);
            int2 s = *(const int2*)(src + i);
            int p0 = atomicAdd(&g_count[d.x], 1);
            if (p0 < CAP) g_bkt[(size_t)d.x * CAP + p0] = s.x;
            int p1 = atomicAdd(&g_count[d.y], 1);
            if (p1 < CAP) g_bkt[(size_t)d.y * CAP + p1] = s.y;
        } else if (i < E) {
            int d = dst[i];
            int p = atomicAdd(&g_count[d], 1);
            if (p < CAP) g_bkt[(size_t)d * CAP + p] = src[i];
        }
    } else {
        int warp = ((blockIdx.x - fillBlocks) * blockDim.x + threadIdx.x) >> 5;
        int lane = threadIdx.x & 31;
        if (warp >= N) return;
        const float4* sv = (const float4*)x;
        float4 a = sv[(size_t)warp * 32 + lane];
        float ss = fmaf(a.x, a.x, fmaf(a.y, a.y, fmaf(a.z, a.z, a.w * a.w)));
        BFLY32(ss);
        float inv = 1.0f / fmaxf(sqrtf(ss), 1e-12f);
        a.x *= inv; a.y *= inv; a.z *= inv; a.w *= inv;
        ((float4*)out)[(size_t)warp * 32 + lane] = a;
        g_h16[0][(size_t)warp * 32 + lane] = f4_to_h4(a);
    }
}

// process one quad of edges (current vA/vB registers)
#define PROCESS_QUAD(vA, vB)                                    \
    {                                                           \
        float dA = dot8(vA, h0, h1, h2, h3);                    \
        float dB = dot8(vB, h0, h1, h2, h3);                    \
        dA += __shfl_xor_sync(0xffffffffu, dA, 8);              \
        dB += __shfl_xor_sync(0xffffffffu, dB, 8);              \
        dA += __shfl_xor_sync(0xffffffffu, dA, 4);              \
        dB += __shfl_xor_sync(0xffffffffu, dB, 4);              \
        dA += __shfl_xor_sync(0xffffffffu, dA, 2);              \
        dB += __shfl_xor_sync(0xffffffffu, dB, 2);              \
        dA += __shfl_xor_sync(0xffffffffu, dA, 1);              \
        dB += __shfl_xor_sync(0xffffffffu, dB, 1);              \
        accum8(acc, vA, sigm(dA));                              \
        accum8(acc, vB, sigm(dB));                              \
    }

// ---- fused hop: segment-16 gather/gate + noise + normalize -----------------
__global__ void __launch_bounds__(256) k_hop(float* __restrict__ out, int N,
                                             int selin, int selout,
                                             uint32_t nk0, uint32_t nk1) {
    __shared__ float xch[8][128];
    int wslot = threadIdx.x >> 5;
    int node = (blockIdx.x * blockDim.x + threadIdx.x) >> 5;
    int lane = threadIdx.x & 31;
    if (node >= N) return;
    int seg = lane >> 4;       // which edge of the pair this lane works on
    int sl = lane & 15;        // lane within segment; owns dims sl*8..sl*8+7
    const uint4* __restrict__ hv = (const uint4*)g_h16[selin];   // 16 uint4/row

    // noise for this lane's 4 output dims — computed UP FRONT so the long
    // independent cipher chain can be scheduled into edge-loop load stalls
    uint32_t nbase = (uint32_t)node * 128u + (uint32_t)lane * 4u;
    float nz0 = tf_normal(nk0, nk1, nbase + 0u);
    float nz1 = tf_normal(nk0, nk1, nbase + 1u);
    float nz2 = tf_normal(nk0, nk1, nbase + 2u);
    float nz3 = tf_normal(nk0, nk1, nbase + 3u);

    uint4 hdu = __ldg(&hv[(size_t)node * 16 + sl]);
    __half2 h0 = *(__half2*)&hdu.x, h1 = *(__half2*)&hdu.y;
    __half2 h2 = *(__half2*)&hdu.z, h3 = *(__half2*)&hdu.w;
    float acc[8] = {0.f, 0.f, 0.f, 0.f, 0.f, 0.f, 0.f, 0.f};

    int cnt = min(g_count[node], CAP);
    const int* bkt = g_bkt + (size_t)node * CAP;
    int nfull = cnt >> 2;     // full quads

    // software-pipelined quad loop: next quad's rows load while current computes
    if (nfull > 0) {
        int sA = __ldg(&bkt[seg]);
        int sB = __ldg(&bkt[2 + seg]);
        uint4 vA = __ldg(&hv[(size_t)sA * 16 + sl]);
        uint4 vB = __ldg(&hv[(size_t)sB * 16 + sl]);
        for (int q = 1; q < nfull; q++) {
            int sA2 = __ldg(&bkt[4 * q + seg]);
            int sB2 = __ldg(&bkt[4 * q + 2 + seg]);
            uint4 vA2 = __ldg(&hv[(size_t)sA2 * 16 + sl]);
            uint4 vB2 = __ldg(&hv[(size_t)sB2 * 16 + sl]);
            PROCESS_QUAD(vA, vB)
            vA = vA2; vB = vB2;
        }
        PROCESS_QUAD(vA, vB)
    }
    int e = nfull * 4;
    if (e + 2 <= cnt) {
        int sA = __ldg(&bkt[e + seg]);
        uint4 vA = __ldg(&hv[(size_t)sA * 16 + sl]);
        float dA = dot8(vA, h0, h1, h2, h3);
        SEGRED(dA);
        accum8(acc, vA, sigm(dA));
        e += 2;
    }
    if (e < cnt) {
        int s = __ldg(&bkt[e]);               // both segments same edge
        uint4 v = __ldg(&hv[(size_t)s * 16 + sl]);
        float d = dot8(v, h0, h1, h2, h3);
        SEGRED(d);
        float a = (seg == 0) ? sigm(d) : 0.f; // avoid double count
        accum8(acc, v, a);
    }

    // cross-segment sum
    #pragma unroll
    for (int i = 0; i < 8; i++)
        acc[i] += __shfl_xor_sync(0xffffffffu, acc[i], 16);

    // layout exchange: dims sl*8..+7 -> float4 per lane over 32 lanes
    if (seg == 0) {
        #pragma unroll
        for (int i = 0; i < 8; i++) xch[wslot][sl * 8 + i] = acc[i];
    }
    __syncwarp();
    float4 r = ((float4*)xch[wslot])[lane];

    // + SIGMA*normal (precomputed regs), l2-normalize, store
    r.x = fmaf(0.1f, nz0, r.x);
    r.y = fmaf(0.1f, nz1, r.y);
    r.z = fmaf(0.1f, nz2, r.z);
    r.w = fmaf(0.1f, nz3, r.w);
    float ss = fmaf(r.x, r.x, fmaf(r.y, r.y, fmaf(r.z, r.z, r.w * r.w)));
    BFLY32(ss);
    float inv = 1.0f / fmaxf(sqrtf(ss), 1e-12f);
    r.x *= inv; r.y *= inv; r.z *= inv; r.w *= inv;
    ((float4*)out)[(size_t)node * 32 + lane] = r;
    if (selout >= 0)
        g_h16[selout][(size_t)node * 32 + lane] = f4_to_h4(r);
}

// ---------------------------------------------------------------------------
extern "C" void kernel_launch(void* const* d_in, const int* in_sizes, int n_in,
                              void* d_out, int out_size) {
    const float* x = (const float*)d_in[0];
    const int* ei = (const int*)d_in[1];      // int32 (JAX x64 disabled)
    int N = in_sizes[0] / DIMS;
    int E = in_sizes[1] / 2;
    float* out = (float*)d_out;
    size_t ND = (size_t)N * DIMS;

    uint32_t hk[3][2];
    for (uint32_t i = 0; i < 3; i++) {
        tf2x32(0u, 1u, 0u, i, hk[i][0], hk[i][1]);
    }

    const int* src = ei;
    const int* dst = ei + E;

    int fillBlocks = ((E + 1) / 2 + 255) / 256;
    int nb = (N + 255) / 256;
    int wNodes = (N + 7) / 8;

    // zero counts, then fused [bucket-fill | normalize(x)]
    k_zero<<<nb, 256>>>(N);
    k_front<<<fillBlocks + wNodes, 256>>>(src, dst, E, x, out, N, fillBlocks);

    // 3 fused hops, ping-pong mirrors (no mirror write on the last hop)
    for (int k = 0; k < 3; k++) {
        float* nxt = out + (size_t)(k + 1) * ND;
        int selout = (k < 2) ? ((k + 1) & 1) : -1;
        k_hop<<<wNodes, 256>>>(nxt, N, k & 1, selout, hk[k][0], hk[k][1]);
    }
}

// round 17
// speedup vs baseline: 1.1650x; 1.1000x over previous
#include <cuda_runtime.h>
#include <cuda_fp16.h>
#include <cstdint>

// ---------------------------------------------------------------------------
// PMWA_24842090840472: 3-hop gated graph aggregation
// R17: R12 verbatim (proven local optimum: 40-reg hop, inline noise epilogue,
//      fused fill|norm front) + two zero-risk shavings:
//      (a) templated hop — last hop skips the unused fp16 mirror store
//      (b) k_zero launch replaced by cudaMemsetAsync on g_count.
// ---------------------------------------------------------------------------

#define DIMS 128
#define NMAX 65537
#define CAP 64

__device__ int g_count[NMAX];
__device__ int g_bkt[(size_t)NMAX * CAP];
// fp16 mirrors of h, ping-pong; row = 32 uint2 = 128 halves (dims in order)
__device__ uint2 g_h16[2][(size_t)NMAX * 32];

// ---------------- Threefry-2x32 (JAX key schedule) -------------------------
#define TF_ROUND(x0, x1, r) \
    do { x0 += x1; x1 = ((x1) << (r)) | ((x1) >> (32 - (r))); x1 ^= x0; } while (0)

__host__ __device__ inline void tf2x32(uint32_t k0, uint32_t k1,
                                       uint32_t x0, uint32_t x1,
                                       uint32_t& o0, uint32_t& o1) {
    uint32_t ks0 = k0, ks1 = k1, ks2 = 0x1BD11BDAu ^ k0 ^ k1;
    x0 += ks0; x1 += ks1;
    TF_ROUND(x0, x1, 13); TF_ROUND(x0, x1, 15); TF_ROUND(x0, x1, 26); TF_ROUND(x0, x1, 6);
    x0 += ks1; x1 += ks2 + 1u;
    TF_ROUND(x0, x1, 17); TF_ROUND(x0, x1, 29); TF_ROUND(x0, x1, 16); TF_ROUND(x0, x1, 24);
    x0 += ks2; x1 += ks0 + 2u;
    TF_ROUND(x0, x1, 13); TF_ROUND(x0, x1, 15); TF_ROUND(x0, x1, 26); TF_ROUND(x0, x1, 6);
    x0 += ks0; x1 += ks1 + 3u;
    TF_ROUND(x0, x1, 17); TF_ROUND(x0, x1, 29); TF_ROUND(x0, x1, 16); TF_ROUND(x0, x1, 24);
    x0 += ks1; x1 += ks2 + 4u;
    TF_ROUND(x0, x1, 13); TF_ROUND(x0, x1, 15); TF_ROUND(x0, x1, 26); TF_ROUND(x0, x1, 6);
    x0 += ks2; x1 += ks0 + 5u;
    o0 = x0; o1 = x1;
}

// XLA/Giles float32 erfinv polynomial
__device__ inline float erfinv_xla(float x) {
    float w = -__logf(fmaf(-x, x, 1.0f));
    float p;
    if (w < 5.0f) {
        w -= 2.5f;
        p = 2.81022636e-08f;
        p = fmaf(p, w, 3.43273939e-07f);
        p = fmaf(p, w, -3.5233877e-06f);
        p = fmaf(p, w, -4.39150654e-06f);
        p = fmaf(p, w, 0.00021858087f);
        p = fmaf(p, w, -0.00125372503f);
        p = fmaf(p, w, -0.00417768164f);
        p = fmaf(p, w, 0.246640727f);
        p = fmaf(p, w, 1.50140941f);
    } else {
        w = sqrtf(w) - 3.0f;
        p = -0.000200214257f;
        p = fmaf(p, w, 0.000100950558f);
        p = fmaf(p, w, 0.00134934322f);
        p = fmaf(p, w, -0.00367342844f);
        p = fmaf(p, w, 0.00573950773f);
        p = fmaf(p, w, -0.0076224613f);
        p = fmaf(p, w, 0.00943887047f);
        p = fmaf(p, w, 1.00167406f);
        p = fmaf(p, w, 2.83297682f);
    }
    return p * x;
}

__device__ inline float tf_normal(uint32_t k0, uint32_t k1, uint32_t idx) {
    uint32_t o0, o1;
    tf2x32(k0, k1, 0u, idx, o0, o1);
    uint32_t bits = o0 ^ o1;
    float f = __uint_as_float(0x3f800000u | (bits >> 9)) - 1.0f;
    float u = fmaf(f, 2.0f, -0.99999994f);
    return 1.41421354f * erfinv_xla(u);
}

// ---------------- helpers --------------------------------------------------
#define BFLY32(d)                                       \
    d += __shfl_xor_sync(0xffffffffu, d, 16);           \
    d += __shfl_xor_sync(0xffffffffu, d, 8);            \
    d += __shfl_xor_sync(0xffffffffu, d, 4);            \
    d += __shfl_xor_sync(0xffffffffu, d, 2);            \
    d += __shfl_xor_sync(0xffffffffu, d, 1);

#define SEGRED(d)                                       \
    d += __shfl_xor_sync(0xffffffffu, d, 8);            \
    d += __shfl_xor_sync(0xffffffffu, d, 4);            \
    d += __shfl_xor_sync(0xffffffffu, d, 2);            \
    d += __shfl_xor_sync(0xffffffffu, d, 1);

__device__ __forceinline__ float sigm(float d) {
    return 1.0f / (1.0f + __expf(-d));
}

__device__ __forceinline__ uint2 f4_to_h4(float4 a) {
    __half2 p0 = __floats2half2_rn(a.x, a.y);
    __half2 p1 = __floats2half2_rn(a.z, a.w);
    uint2 u;
    u.x = *(uint32_t*)&p0;
    u.y = *(uint32_t*)&p1;
    return u;
}

// partial dot over this lane's 8 dims (uint4 = 4 half2), fp16 products/f32 tail
__device__ __forceinline__ float dot8(uint4 v, __half2 h0, __half2 h1,
                                      __half2 h2, __half2 h3) {
    __half2 p = __hmul2(*(__half2*)&v.x, h0);
    p = __hfma2(*(__half2*)&v.y, h1, p);
    p = __hfma2(*(__half2*)&v.z, h2, p);
    p = __hfma2(*(__half2*)&v.w, h3, p);
    float2 f = __half22float2(p);
    return f.x + f.y;
}

__device__ __forceinline__ void accum8(float* acc, uint4 v, float a) {
    float2 f0 = __half22float2(*(__half2*)&v.x);
    float2 f1 = __half22float2(*(__half2*)&v.y);
    float2 f2 = __half22float2(*(__half2*)&v.z);
    float2 f3 = __half22float2(*(__half2*)&v.w);
    acc[0] = fmaf(a, f0.x, acc[0]);
    acc[1] = fmaf(a, f0.y, acc[1]);
    acc[2] = fmaf(a, f1.x, acc[2]);
    acc[3] = fmaf(a, f1.y, acc[3]);
    acc[4] = fmaf(a, f2.x, acc[4]);
    acc[5] = fmaf(a, f2.y, acc[5]);
    acc[6] = fmaf(a, f3.x, acc[6]);
    acc[7] = fmaf(a, f3.y, acc[7]);
}

// ------- fused: bucket fill (first fillBlocks) | normalize x (rest) --------
__global__ void k_front(const int* __restrict__ src, const int* __restrict__ dst,
                        int E, const float* __restrict__ x,
                        float* __restrict__ out, int N, int fillBlocks) {
    if ((int)blockIdx.x < fillBlocks) {
        int i = (blockIdx.x * blockDim.x + threadIdx.x) * 2;
        if (i + 1 < E) {
            int2 d = *(const int2*)(dst + i);
            int2 s = *(const int2*)(src + i);
            int p0 = atomicAdd(&g_count[d.x], 1);
            if (p0 < CAP) g_bkt[(size_t)d.x * CAP + p0] = s.x;
            int p1 = atomicAdd(&g_count[d.y], 1);
            if (p1 < CAP) g_bkt[(size_t)d.y * CAP + p1] = s.y;
        } else if (i < E) {
            int d = dst[i];
            int p = atomicAdd(&g_count[d], 1);
            if (p < CAP) g_bkt[(size_t)d * CAP + p] = src[i];
        }
    } else {
        int warp = ((blockIdx.x - fillBlocks) * blockDim.x + threadIdx.x) >> 5;
        int lane = threadIdx.x & 31;
        if (warp >= N) return;
        const float4* sv = (const float4*)x;
        float4 a = sv[(size_t)warp * 32 + lane];
        float ss = fmaf(a.x, a.x, fmaf(a.y, a.y, fmaf(a.z, a.z, a.w * a.w)));
        BFLY32(ss);
        float inv = 1.0f / fmaxf(sqrtf(ss), 1e-12f);
        a.x *= inv; a.y *= inv; a.z *= inv; a.w *= inv;
        ((float4*)out)[(size_t)warp * 32 + lane] = a;
        g_h16[0][(size_t)warp * 32 + lane] = f4_to_h4(a);
    }
}

// ---- fused hop: segment-16 gather/gate + noise + normalize -----------------
template <bool WRITE_MIRROR>
__global__ void __launch_bounds__(256) k_hop(float* __restrict__ out, int N,
                                             int selin, int selout,
                                             uint32_t nk0, uint32_t nk1) {
    __shared__ float xch[8][128];
    int wslot = threadIdx.x >> 5;
    int node = (blockIdx.x * blockDim.x + threadIdx.x) >> 5;
    int lane = threadIdx.x & 31;
    if (node >= N) return;
    int seg = lane >> 4;       // which edge of the pair this lane works on
    int sl = lane & 15;        // lane within segment; owns dims sl*8..sl*8+7
    const uint4* __restrict__ hv = (const uint4*)g_h16[selin];   // 16 uint4/row

    uint4 hdu = __ldg(&hv[(size_t)node * 16 + sl]);
    __half2 h0 = *(__half2*)&hdu.x, h1 = *(__half2*)&hdu.y;
    __half2 h2 = *(__half2*)&hdu.z, h3 = *(__half2*)&hdu.w;
    float acc[8] = {0.f, 0.f, 0.f, 0.f, 0.f, 0.f, 0.f, 0.f};

    int cnt = min(g_count[node], CAP);
    const int* bkt = g_bkt + (size_t)node * CAP;
    int e = 0;

    // 4 edges per iteration (2 segment-pairs in flight)
    for (; e + 4 <= cnt; e += 4) {
        int sA = __ldg(&bkt[e + seg]);
        int sB = __ldg(&bkt[e + 2 + seg]);
        uint4 vA = __ldg(&hv[(size_t)sA * 16 + sl]);
        uint4 vB = __ldg(&hv[(size_t)sB * 16 + sl]);
        float dA = dot8(vA, h0, h1, h2, h3);
        float dB = dot8(vB, h0, h1, h2, h3);
        #pragma unroll
        for (int off = 8; off >= 1; off >>= 1) {
            dA += __shfl_xor_sync(0xffffffffu, dA, off);
            dB += __shfl_xor_sync(0xffffffffu, dB, off);
        }
        accum8(acc, vA, sigm(dA));
        accum8(acc, vB, sigm(dB));
    }
    if (e + 2 <= cnt) {
        int sA = __ldg(&bkt[e + seg]);
        uint4 vA = __ldg(&hv[(size_t)sA * 16 + sl]);
        float dA = dot8(vA, h0, h1, h2, h3);
        SEGRED(dA);
        accum8(acc, vA, sigm(dA));
        e += 2;
    }
    if (e < cnt) {
        int s = __ldg(&bkt[e]);               // both segments same edge
        uint4 v = __ldg(&hv[(size_t)s * 16 + sl]);
        float d = dot8(v, h0, h1, h2, h3);
        SEGRED(d);
        float a = (seg == 0) ? sigm(d) : 0.f; // avoid double count
        accum8(acc, v, a);
    }

    // cross-segment sum
    #pragma unroll
    for (int i = 0; i < 8; i++)
        acc[i] += __shfl_xor_sync(0xffffffffu, acc[i], 16);

    // layout exchange: dims sl*8..+7 -> float4 per lane over 32 lanes
    if (seg == 0) {
        #pragma unroll
        for (int i = 0; i < 8; i++) xch[wslot][sl * 8 + i] = acc[i];
    }
    __syncwarp();
    float4 r = ((float4*)xch[wslot])[lane];

    // + SIGMA*normal, l2-normalize, store f32 out (+ fp16 mirror)
    uint32_t base = (uint32_t)node * 128u + (uint32_t)lane * 4u;
    r.x = fmaf(0.1f, tf_normal(nk0, nk1, base + 0u), r.x);
    r.y = fmaf(0.1f, tf_normal(nk0, nk1, base + 1u), r.y);
    r.z = fmaf(0.1f, tf_normal(nk0, nk1, base + 2u), r.z);
    r.w = fmaf(0.1f, tf_normal(nk0, nk1, base + 3u), r.w);
    float ss = fmaf(r.x, r.x, fmaf(r.y, r.y, fmaf(r.z, r.z, r.w * r.w)));
    BFLY32(ss);
    float inv = 1.0f / fmaxf(sqrtf(ss), 1e-12f);
    r.x *= inv; r.y *= inv; r.z *= inv; r.w *= inv;
    ((float4*)out)[(size_t)node * 32 + lane] = r;
    if (WRITE_MIRROR)
        g_h16[selout][(size_t)node * 32 + lane] = f4_to_h4(r);
}

// ---------------------------------------------------------------------------
extern "C" void kernel_launch(void* const* d_in, const int* in_sizes, int n_in,
                              void* d_out, int out_size) {
    const float* x = (const float*)d_in[0];
    const int* ei = (const int*)d_in[1];      // int32 (JAX x64 disabled)
    int N = in_sizes[0] / DIMS;
    int E = in_sizes[1] / 2;
    float* out = (float*)d_out;
    size_t ND = (size_t)N * DIMS;

    uint32_t hk[3][2];
    for (uint32_t i = 0; i < 3; i++) {
        tf2x32(0u, 1u, 0u, i, hk[i][0], hk[i][1]);
    }

    const int* src = ei;
    const int* dst = ei + E;

    int fillBlocks = ((E + 1) / 2 + 255) / 256;
    int wNodes = (N + 7) / 8;

    // zero counts via memset node (replaces the k_zero launch)
    void* countPtr = nullptr;
    cudaGetSymbolAddress(&countPtr, g_count);
    cudaMemsetAsync(countPtr, 0, (size_t)N * sizeof(int));

    // fused [bucket-fill | normalize(x)]
    k_front<<<fillBlocks + wNodes, 256>>>(src, dst, E, x, out, N, fillBlocks);

    // 3 fused hops; last one skips the fp16 mirror store
    k_hop<true><<<wNodes, 256>>>(out + 1 * ND, N, 0, 1, hk[0][0], hk[0][1]);
    k_hop<true><<<wNodes, 256>>>(out + 2 * ND, N, 1, 0, hk[1][0], hk[1][1]);
    k_hop<false><<<wNodes, 256>>>(out + 3 * ND, N, 0, 1, hk[2][0], hk[2][1]);
}